// round 17
// baseline (speedup 1.0000x reference)
#include <cuda_runtime.h>
#include <cuda_bf16.h>
#include <math.h>
#include <cstdint>

// Problem dims (fixed by the reference)
#define NP      128      // proposals
#define NB      16       // neighbors per proposal
#define KK      64       // knn per node
#define LL      1024     // NB*KK flattened group size
#define MM      450      // FINEMATCH_MAX_POINT
#define DD      256      // feature dim
#define NPTS_C  20000
#define NROWS   (NP * MM)   // 57600

#define ROWS_PER_BLK 32     // rows per feat-copy block (32KB smem tile)

// Scratch: per-output-row resolved feature index (-1 => zero row)
__device__ int g_rowfidx[NROWS];
// Zero source row for invalid rows (static storage -> zero-initialized)
__device__ __align__(128) float g_zero[DD];

__device__ __forceinline__ uint32_t smem_u32(const void* p) {
    uint32_t a;
    asm("{ .reg .u64 t; cvta.to.shared.u64 t, %1; cvt.u32.u64 %0, t; }"
        : "=r"(a) : "l"(p));
    return a;
}

// ---------------------------------------------------------------------------
// Kernel A: mask eval + stable compaction (smem) + resample + write points,
// mask, and per-row feature indices. One block (1024 thr) per proposal.
// Stable ascending-j order matches jnp.argsort(stable) of !mask.
// Resample: single-rounded fp32 floor((i*n)/450); i*n < 2^24 exact, IEEE
// divide exact at integer quotients — bit-matches XLA's (i/M)*n rewrite.
// ---------------------------------------------------------------------------
__global__ void __launch_bounds__(1024) compact_kernel(
    const unsigned int*  __restrict__ nb_mask,     // [P, NB] bool-as-u32
    const int*           __restrict__ seed_idx,    // [P, NB] int32
    const unsigned int*  __restrict__ knn_masks,   // [NNODES, K] bool-as-u32
    const int*           __restrict__ knn_idx,     // [NNODES, K]
    const float*         __restrict__ knn_points,  // [NNODES, K, 3]
    float*               __restrict__ out)
{
    __shared__ int   s_fidx[LL];
    __shared__ float s_px[LL];
    __shared__ float s_py[LL];
    __shared__ float s_pz[LL];
    __shared__ int   s_wsum[32];
    __shared__ int   s_woff[32];
    __shared__ int   s_n;

    const int p    = blockIdx.x;
    const int j    = threadIdx.x;      // 0..1023
    const int lane = j & 31;
    const int warp = j >> 5;

    // ---- Phase 1: compaction into smem ----
    {
        const int nb = j >> 6;
        const int kk = j & 63;
        const int node = seed_idx[p * NB + nb];
        const int gk   = node * KK + kk;
        const bool m = (knn_masks[gk] != 0u) && (nb_mask[p * NB + nb] != 0u);

        int   fi = 0;
        float px = 0.f, py = 0.f, pz = 0.f;
        if (m) {
            fi = knn_idx[gk];
            px = knn_points[gk * 3 + 0];
            py = knn_points[gk * 3 + 1];
            pz = knn_points[gk * 3 + 2];
        }

        const unsigned ball = __ballot_sync(0xffffffffu, m);
        const int wpre = __popc(ball & ((1u << lane) - 1u));
        if (lane == 0) s_wsum[warp] = __popc(ball);
        __syncthreads();

        if (warp == 0) {
            int v = s_wsum[lane];
            int s = v;
            #pragma unroll
            for (int d = 1; d < 32; d <<= 1) {
                int t = __shfl_up_sync(0xffffffffu, s, d);
                if (lane >= d) s += t;
            }
            s_woff[lane] = s - v;
            if (lane == 31) s_n = s;
        }
        __syncthreads();

        if (m) {
            const int slot = s_woff[warp] + wpre;
            s_fidx[slot] = fi;
            s_px[slot] = px;
            s_py[slot] = py;
            s_pz[slot] = pz;
        }
        __syncthreads();
    }

    // ---- Phase 2: resample, write points + mask + row fidx ----
    const int n  = s_n;
    const int nm = (n < MM) ? n : MM;

    const size_t MASK_OFF = (size_t)NP * MM * 3 + (size_t)NP * MM * DD;

    const int i = j;
    if (i < MM) {
        const size_t row = (size_t)p * MM + i;
        if (i < nm) {
            int local;
            if (n > MM) {
                local = __float2int_rd(__fdiv_rn((float)(i * n), (float)MM));
            } else {
                local = i;
            }
            if (local > LL - 1) local = LL - 1;

            out[row * 3 + 0]    = s_px[local];
            out[row * 3 + 1]    = s_py[local];
            out[row * 3 + 2]    = s_pz[local];
            out[MASK_OFF + row] = 1.0f;
            const int f = s_fidx[local];
            g_rowfidx[row] = (f >= 0 && f < NPTS_C) ? f : -1;
        } else {
            out[row * 3 + 0]    = 0.0f;
            out[row * 3 + 1]    = 0.0f;
            out[row * 3 + 2]    = 0.0f;
            out[MASK_OFF + row] = 0.0f;
            g_rowfidx[row] = -1;
        }
    }

    asm volatile("griddepcontrol.launch_dependents;" ::: "memory");
}

// ---------------------------------------------------------------------------
// Kernel B: feature copy via bulk-async (TMA) — bypasses the LSU/L1tex
// wavefront path that bound the LDG/STG version (64 wavefronts/row).
// Each block: 32 threads, 32KB smem tile, 32 rows.
//   - thread t issues a 1KB cp.async.bulk g->s for its row (or g_zero)
//   - one mbarrier accumulates 32KB of complete_tx
//   - thread 0 issues ONE 32KB cp.async.bulk s->g (output rows contiguous)
// 1800 blocks exactly cover 57600 rows.
// ---------------------------------------------------------------------------
__global__ void __launch_bounds__(32) feat_kernel(
    const float* __restrict__ feats,    // [NPTS, D]
    float*       __restrict__ out)
{
    __shared__ __align__(128) float s_buf[ROWS_PER_BLK * DD];   // 32 KB
    __shared__ __align__(8) unsigned long long s_mbar;

    asm volatile("griddepcontrol.wait;" ::: "memory");

    const int t  = threadIdx.x;                 // 0..31
    const int rb = blockIdx.x * ROWS_PER_BLK;
    const size_t FEATS_OFF = (size_t)NP * MM * 3;

    const uint32_t mbar = smem_u32(&s_mbar);

    if (t == 0) {
        asm volatile("mbarrier.init.shared.b64 [%0], %1;"
                     :: "r"(mbar), "r"(1) : "memory");
    }
    __syncwarp();

    const int f = g_rowfidx[rb + t];
    const float* src = (f >= 0) ? (feats + (size_t)f * DD) : g_zero;

    if (t == 0) {
        asm volatile("mbarrier.arrive.expect_tx.shared.b64 _, [%0], %1;"
                     :: "r"(mbar), "r"(ROWS_PER_BLK * DD * 4) : "memory");
    }
    __syncwarp();   // expect_tx visible before any load can complete-tx

    const uint32_t dst_s = smem_u32(s_buf) + (uint32_t)t * (DD * 4);
    asm volatile(
        "cp.async.bulk.shared::cta.global.mbarrier::complete_tx::bytes "
        "[%0], [%1], %2, [%3];"
        :: "r"(dst_s), "l"(src), "r"(DD * 4), "r"(mbar) : "memory");

    // wait for all 32KB to land (phase parity 0)
    {
        uint32_t done;
        asm volatile(
            "{\n\t.reg .pred p;\n\t"
            "mbarrier.try_wait.parity.acquire.cta.shared::cta.b64 p, [%1], %2;\n\t"
            "selp.b32 %0, 1, 0, p;\n\t}"
            : "=r"(done) : "r"(mbar), "r"(0) : "memory");
        if (!done) {
            asm volatile(
                "{\n\t.reg .pred P1;\n\t"
                "WL_%=:\n\t"
                "mbarrier.try_wait.parity.acquire.cta.shared::cta.b64 P1, [%0], %1, 0x989680;\n\t"
                "@P1 bra.uni WD_%=;\n\t"
                "bra.uni WL_%=;\n\t"
                "WD_%=:\n\t}"
                :: "r"(mbar), "r"(0) : "memory");
        }
    }

    if (t == 0) {
        float* gdst = out + FEATS_OFF + (size_t)rb * DD;
        asm volatile(
            "cp.async.bulk.global.shared::cta.bulk_group [%0], [%1], %2;"
            :: "l"(gdst), "r"(smem_u32(s_buf)), "r"(ROWS_PER_BLK * DD * 4)
            : "memory");
        asm volatile("cp.async.bulk.commit_group;" ::: "memory");
        asm volatile("cp.async.bulk.wait_group 0;" ::: "memory");
    }
}

extern "C" void kernel_launch(void* const* d_in, const int* in_sizes, int n_in,
                              void* d_out, int out_size)
{
    // metadata order (= setup_inputs dict order):
    // 0: ref_node_neighbor_mask   (P, NB)        bool -> u32
    // 1: ref_seed_neighbor_indices(P, NB)        int32
    // 2: ref_node_knn_masks       (NNODES, K)    bool -> u32
    // 3: ref_node_knn_points      (NNODES, K, 3) float32
    // 4: ref_node_knn_indices     (NNODES, K)    int32
    // 5: ref_feats_m              (NPTS, D)      float32
    const unsigned int*  nb_mask    = (const unsigned int*)d_in[0];
    const int*           seed_idx   = (const int*)d_in[1];
    const unsigned int*  knn_masks  = (const unsigned int*)d_in[2];
    const float*         knn_points = (const float*)d_in[3];
    const int*           knn_idx    = (const int*)d_in[4];
    const float*         feats      = (const float*)d_in[5];
    float* out = (float*)d_out;

    compact_kernel<<<NP, 1024>>>(nb_mask, seed_idx, knn_masks, knn_idx,
                                 knn_points, out);

    // PDL launch: feat_kernel ramps while compact_kernel drains.
    cudaLaunchConfig_t cfg = {};
    cfg.gridDim  = dim3(NROWS / ROWS_PER_BLK);   // 1800 blocks
    cfg.blockDim = dim3(32);
    cfg.dynamicSmemBytes = 0;
    cfg.stream = 0;
    cudaLaunchAttribute attr[1];
    attr[0].id = cudaLaunchAttributeProgrammaticStreamSerialization;
    attr[0].val.programmaticStreamSerializationAllowed = 1;
    cfg.attrs = attr;
    cfg.numAttrs = 1;
    cudaLaunchKernelEx(&cfg, feat_kernel, feats, out);
}